// round 6
// baseline (speedup 1.0000x reference)
#include <cuda_runtime.h>

// WavePool3D: 3D Haar wavelet pooling, kernel=stride=2.
// Input  x: [1, 32, 128, 128, 128] fp32 (W contiguous)
// Output  : [8, 1, 32, 64, 64, 64] fp32 (8 subbands LLL..HHH, contiguous)
//
// v5: persistent grid-stride version of v1 (best variant). Exactly one
// resident wave (148 SMs x 8 blocks x 256 thr) loops over all 4,194,304
// tiles. Removes per-CTA launch/drain churn; cross-iteration scoreboarding
// keeps 4 LDG.128 in flight per warp continuously. Math/addressing per
// tile identical to v1 (the 75.1us / DRAM 81.4% kernel).

#define C_DIM   32
#define DO_DIM  64
#define HO_DIM  64
#define WQ_DIM  32

#define IN_W    128
#define IN_HW   (128 * 128)
#define IN_DHW  (128 * 128 * 128)

#define OUT_W   64
#define OUT_HW  (64 * 64)
#define OUT_DHW (64 * 64 * 64)
#define OUT_CDHW (C_DIM * OUT_DHW)   // stride between subbands

#define TOTAL_TILES (C_DIM * DO_DIM * HO_DIM * WQ_DIM)  // 4,194,304

__global__ __launch_bounds__(256)
void wavepool3d_kernel(const float* __restrict__ x, float* __restrict__ out)
{
    const unsigned stride = gridDim.x * blockDim.x;
    const float scale = 0.35355339059327378f;  // 1/(2*sqrt(2))

    for (unsigned idx = blockIdx.x * blockDim.x + threadIdx.x;
         idx < TOTAL_TILES; idx += stride)
    {
        // idx layout: [c:5][d:6][h:6][wq:5]  -> wq fastest for coalescing
        unsigned wq = idx & 31u;
        unsigned h  = (idx >> 5) & 63u;
        unsigned d  = (idx >> 11) & 63u;
        unsigned c  = idx >> 17;

        const float* base = x + (size_t)c * IN_DHW
                              + (size_t)(2u * d) * IN_HW
                              + (size_t)(2u * h) * IN_W
                              + 4u * wq;

        float4 a00 = __ldcs(reinterpret_cast<const float4*>(base));
        float4 a01 = __ldcs(reinterpret_cast<const float4*>(base + IN_W));
        float4 a10 = __ldcs(reinterpret_cast<const float4*>(base + IN_HW));
        float4 a11 = __ldcs(reinterpret_cast<const float4*>(base + IN_HW + IN_W));

        float2 r[8];  // r[f].x = output w pos 2*wq, .y = 2*wq+1

        #pragma unroll
        for (int p = 0; p < 2; p++) {
            float s00_0 = p ? a00.z : a00.x, s00_1 = p ? a00.w : a00.y;
            float s01_0 = p ? a01.z : a01.x, s01_1 = p ? a01.w : a01.y;
            float s10_0 = p ? a10.z : a10.x, s10_1 = p ? a10.w : a10.y;
            float s11_0 = p ? a11.z : a11.x, s11_1 = p ? a11.w : a11.y;

            // k-axis (W)
            float e00 = s00_0 + s00_1, o00 = s00_1 - s00_0;
            float e01 = s01_0 + s01_1, o01 = s01_1 - s01_0;
            float e10 = s10_0 + s10_1, o10 = s10_1 - s10_0;
            float e11 = s11_0 + s11_1, o11 = s11_1 - s11_0;
            // j-axis (H)
            float le0 = e00 + e01, he0 = e01 - e00;
            float le1 = e10 + e11, he1 = e11 - e10;
            float lo0 = o00 + o01, ho0 = o01 - o00;
            float lo1 = o10 + o11, ho1 = o11 - o10;
            // i-axis (D)
            float f0 = (le0 + le1) * scale;   // LLL
            float f1 = (lo0 + lo1) * scale;   // LLH
            float f2 = (he0 + he1) * scale;   // LHL
            float f3 = (ho0 + ho1) * scale;   // LHH
            float f4 = (le1 - le0) * scale;   // HLL
            float f5 = (lo1 - lo0) * scale;   // HLH
            float f6 = (he1 - he0) * scale;   // HHL
            float f7 = (ho1 - ho0) * scale;   // HHH

            if (p == 0) {
                r[0].x = f0; r[1].x = f1; r[2].x = f2; r[3].x = f3;
                r[4].x = f4; r[5].x = f5; r[6].x = f6; r[7].x = f7;
            } else {
                r[0].y = f0; r[1].y = f1; r[2].y = f2; r[3].y = f3;
                r[4].y = f4; r[5].y = f5; r[6].y = f6; r[7].y = f7;
            }
        }

        float* obase = out + (size_t)c * OUT_DHW
                           + (size_t)d * OUT_HW
                           + (size_t)h * OUT_W
                           + 2u * wq;
        #pragma unroll
        for (int f = 0; f < 8; f++) {
            __stcs(reinterpret_cast<float2*>(obase + (size_t)f * OUT_CDHW), r[f]);
        }
    }
}

extern "C" void kernel_launch(void* const* d_in, const int* in_sizes, int n_in,
                              void* d_out, int out_size)
{
    const float* x = (const float*)d_in[0];
    float* out = (float*)d_out;

    // One resident wave: 148 SMs x 8 blocks/SM (256 thr, ~40 regs -> fits)
    const unsigned grid = 148 * 8;   // 1184 blocks
    wavepool3d_kernel<<<grid, 256>>>(x, out);
}

// round 7
// speedup vs baseline: 1.1318x; 1.1318x over previous
#include <cuda_runtime.h>

// WavePool3D: 3D Haar wavelet pooling, kernel=stride=2.
// Input  x: [1, 32, 128, 128, 128] fp32 (W contiguous)
// Output  : [8, 1, 32, 64, 64, 64] fp32 (8 subbands LLL..HHH, contiguous)
//
// v6: Blackwell 256-bit loads. Each thread owns 8 CONSECUTIVE W elements
// (one w-octet): 4x ld.global.v8.f32 (2x2 D/H rows, 32B/lane) -> per-warp
// load instruction = 1024B fully contiguous. Butterfly yields 4 output w
// per subband -> 8x STG.128; lanes 0-15 cover one output h-row (256B),
// lanes 16-31 the next (adjacent in memory) -> 512B contiguous per store
// instruction. Half the memory requests per byte vs v1 on both streams.

#define C_DIM   32
#define DO_DIM  64
#define HO_DIM  64
#define WG_DIM  16   // 16 groups of 8 W-elements = 128 input W

#define IN_W    128
#define IN_HW   (128 * 128)
#define IN_DHW  (128 * 128 * 128)

#define OUT_W   64
#define OUT_HW  (64 * 64)
#define OUT_DHW (64 * 64 * 64)
#define OUT_CDHW (C_DIM * OUT_DHW)   // stride between subbands

__device__ __forceinline__ void ldg_v8(const float* p, float v[8])
{
    asm volatile(
        "ld.global.v8.f32 {%0,%1,%2,%3,%4,%5,%6,%7}, [%8];"
        : "=f"(v[0]), "=f"(v[1]), "=f"(v[2]), "=f"(v[3]),
          "=f"(v[4]), "=f"(v[5]), "=f"(v[6]), "=f"(v[7])
        : "l"(p));
}

__global__ __launch_bounds__(256, 4)
void wavepool3d_kernel(const float* __restrict__ x, float* __restrict__ out)
{
    unsigned idx = blockIdx.x * blockDim.x + threadIdx.x;
    // idx layout: [c:5][d:6][h:6][wg:4]  -> wg fastest for coalescing
    unsigned wg = idx & 15u;
    unsigned h  = (idx >> 4) & 63u;
    unsigned d  = (idx >> 10) & 63u;
    unsigned c  = idx >> 16;

    // Input base: x[c][2d + i][2h + j][8*wg .. 8*wg+7]  (32B aligned)
    const float* base = x + (size_t)c * IN_DHW
                          + (size_t)(2u * d) * IN_HW
                          + (size_t)(2u * h) * IN_W
                          + 8u * wg;

    float a00[8], a01[8], a10[8], a11[8];
    ldg_v8(base,                a00);
    ldg_v8(base + IN_W,         a01);
    ldg_v8(base + IN_HW,        a10);
    ldg_v8(base + IN_HW + IN_W, a11);

    const float scale = 0.35355339059327378f;  // 1/(2*sqrt(2))

    float4 r[8];  // r[f] = 4 output w positions for subband f
    float* rf = reinterpret_cast<float*>(r);   // rf[f*4 + p]

    #pragma unroll
    for (int p = 0; p < 4; p++) {
        float s00_0 = a00[2*p], s00_1 = a00[2*p + 1];
        float s01_0 = a01[2*p], s01_1 = a01[2*p + 1];
        float s10_0 = a10[2*p], s10_1 = a10[2*p + 1];
        float s11_0 = a11[2*p], s11_1 = a11[2*p + 1];

        // k-axis (W)
        float e00 = s00_0 + s00_1, o00 = s00_1 - s00_0;
        float e01 = s01_0 + s01_1, o01 = s01_1 - s01_0;
        float e10 = s10_0 + s10_1, o10 = s10_1 - s10_0;
        float e11 = s11_0 + s11_1, o11 = s11_1 - s11_0;
        // j-axis (H)
        float le0 = e00 + e01, he0 = e01 - e00;
        float le1 = e10 + e11, he1 = e11 - e10;
        float lo0 = o00 + o01, ho0 = o01 - o00;
        float lo1 = o10 + o11, ho1 = o11 - o10;
        // i-axis (D)
        rf[0*4 + p] = (le0 + le1) * scale;   // LLL
        rf[1*4 + p] = (lo0 + lo1) * scale;   // LLH
        rf[2*4 + p] = (he0 + he1) * scale;   // LHL
        rf[3*4 + p] = (ho0 + ho1) * scale;   // LHH
        rf[4*4 + p] = (le1 - le0) * scale;   // HLL
        rf[5*4 + p] = (lo1 - lo0) * scale;   // HLH
        rf[6*4 + p] = (he1 - he0) * scale;   // HHL
        rf[7*4 + p] = (ho1 - ho0) * scale;   // HHH
    }

    // out[f][c][d][h][4*wg .. 4*wg+3]  -> STG.128, 512B contiguous per warp
    float* obase = out + (size_t)c * OUT_DHW
                       + (size_t)d * OUT_HW
                       + (size_t)h * OUT_W
                       + 4u * wg;
    #pragma unroll
    for (int f = 0; f < 8; f++) {
        *reinterpret_cast<float4*>(obase + (size_t)f * OUT_CDHW) = r[f];
    }
}

extern "C" void kernel_launch(void* const* d_in, const int* in_sizes, int n_in,
                              void* d_out, int out_size)
{
    const float* x = (const float*)d_in[0];
    float* out = (float*)d_out;

    // total threads = 32 * 64 * 64 * 16 = 2,097,152 -> 8192 blocks x 256
    const unsigned total = C_DIM * DO_DIM * HO_DIM * WG_DIM;
    const unsigned block = 256;
    wavepool3d_kernel<<<total / block, block>>>(x, out);
}